// round 1
// baseline (speedup 1.0000x reference)
#include <cuda_runtime.h>

#define MAXN 100000
#define F 64

// Scratch (allocation-free rule: __device__ globals)
__device__ float g_deg[MAXN];
__device__ float g_dinv[MAXN];
__device__ float g_hs[(size_t)MAXN * F];   // scaled features h*dinv[row]
__device__ float g_acc[(size_t)MAXN * F];  // scatter accumulator

__global__ void k_deg_init(int N) {
    int i = blockIdx.x * blockDim.x + threadIdx.x;
    if (i < N) g_deg[i] = 1.0f;  // self-loop contributes 1
}

__global__ void k_deg_count(const int* __restrict__ dst, int E) {
    int e = blockIdx.x * blockDim.x + threadIdx.x;
    if (e < E) atomicAdd(&g_deg[dst[e]], 1.0f);
}

__global__ void k_dinv(int N) {
    int i = blockIdx.x * blockDim.x + threadIdx.x;
    if (i < N) g_dinv[i] = rsqrtf(g_deg[i]);
}

// Scatter: acc[dst] += hs[src]  (norm factored out: dinv[src] already in hs,
// dinv[dst] applied in the consuming GEMM's input epilogue).
// 16 threads per edge, float4 each -> coalesced 256B row gather + vector RED.
__global__ void k_scatter(const int* __restrict__ src, const int* __restrict__ dst, int E) {
    int t = blockIdx.x * blockDim.x + threadIdx.x;
    int e = t >> 4;
    if (e >= E) return;
    int c = t & 15;
    int s = src[e];
    int d = dst[e];
    float4 v = *(const float4*)&g_hs[(size_t)s * F + c * 4];
    float* p = &g_acc[(size_t)d * F + c * 4];
    asm volatile("red.global.add.v4.f32 [%0], {%1,%2,%3,%4};"
                 :: "l"(p), "f"(v.x), "f"(v.y), "f"(v.z), "f"(v.w)
                 : "memory");
}

// Fused GEMM:
//  MODE 0: in = x[row];                              hs = (in@W)*dinv; acc row = 0
//  MODE 1: in = relu(dinv*(acc+hs)+b_in);            hs = (in@W)*dinv; acc row = 0
//  MODE 2: in = relu(dinv*(acc+hs)+b_in);            out = in@W + b_out   (NOUT=32)
template <int NOUT, int MODE>
__global__ void __launch_bounds__(256)
k_gemm(const float* __restrict__ xin, const float* __restrict__ W,
       const float* __restrict__ b_in, const float* __restrict__ b_out,
       float* __restrict__ out, int N) {
    __shared__ float sW[F * NOUT];
    {
        const float4* W4 = (const float4*)W;
        float4* sW4 = (float4*)sW;
        for (int i = threadIdx.x; i < F * NOUT / 4; i += 256) sW4[i] = W4[i];
    }
    __syncthreads();

    int row = blockIdx.x * 256 + threadIdx.x;
    if (row >= N) return;

    float racc[NOUT];
#pragma unroll
    for (int j = 0; j < NOUT; j++) racc[j] = 0.0f;

    float d = g_dinv[row];
    const float4* xr4 = (const float4*)(xin + (size_t)row * F);
    const float4* ar4 = (const float4*)(g_acc + (size_t)row * F);
    const float4* hr4 = (const float4*)(g_hs + (size_t)row * F);
    const float4* b4  = (const float4*)b_in;

    for (int kk = 0; kk < F / 4; kk++) {
        float4 xv;
        if (MODE == 0) {
            xv = xr4[kk];
        } else {
            float4 a = ar4[kk], h = hr4[kk], bb = b4[kk];
            xv.x = fmaxf(fmaf(d, a.x + h.x, bb.x), 0.0f);
            xv.y = fmaxf(fmaf(d, a.y + h.y, bb.y), 0.0f);
            xv.z = fmaxf(fmaf(d, a.z + h.z, bb.z), 0.0f);
            xv.w = fmaxf(fmaf(d, a.w + h.w, bb.w), 0.0f);
        }
        float vk[4] = {xv.x, xv.y, xv.z, xv.w};
#pragma unroll
        for (int u = 0; u < 4; u++) {
            const float4* wr = (const float4*)&sW[(kk * 4 + u) * NOUT];
            float v = vk[u];
#pragma unroll
            for (int j = 0; j < NOUT / 4; j++) {
                float4 w = wr[j];
                racc[4 * j + 0] = fmaf(v, w.x, racc[4 * j + 0]);
                racc[4 * j + 1] = fmaf(v, w.y, racc[4 * j + 1]);
                racc[4 * j + 2] = fmaf(v, w.z, racc[4 * j + 2]);
                racc[4 * j + 3] = fmaf(v, w.w, racc[4 * j + 3]);
            }
        }
    }

    if (MODE == 2) {
        float4* o4 = (float4*)(out + (size_t)row * NOUT);
        const float4* bo4 = (const float4*)b_out;
#pragma unroll
        for (int j = 0; j < NOUT / 4; j++) {
            float4 bo = bo4[j];
            float4 r;
            r.x = racc[4 * j + 0] + bo.x;
            r.y = racc[4 * j + 1] + bo.y;
            r.z = racc[4 * j + 2] + bo.z;
            r.w = racc[4 * j + 3] + bo.w;
            o4[j] = r;
        }
    } else {
        float4* hw4 = (float4*)(g_hs + (size_t)row * F);
        float4* aw4 = (float4*)(g_acc + (size_t)row * F);
#pragma unroll
        for (int j = 0; j < NOUT / 4; j++) {
            float4 r;
            r.x = racc[4 * j + 0] * d;
            r.y = racc[4 * j + 1] * d;
            r.z = racc[4 * j + 2] * d;
            r.w = racc[4 * j + 3] * d;
            hw4[j] = r;
            aw4[j] = make_float4(0.0f, 0.0f, 0.0f, 0.0f);  // prep for next scatter
        }
    }
}

extern "C" void kernel_launch(void* const* d_in, const int* in_sizes, int n_in,
                              void* d_out, int out_size) {
    const float* x  = (const float*)d_in[0];
    const int*   ei = (const int*)d_in[1];
    const float* W1 = (const float*)d_in[2];
    const float* b1 = (const float*)d_in[3];
    const float* W2 = (const float*)d_in[4];
    const float* b2 = (const float*)d_in[5];
    const float* Wl = (const float*)d_in[6];
    const float* bl = (const float*)d_in[7];
    float* out = (float*)d_out;

    int N = in_sizes[0] / F;
    int E = in_sizes[1] / 2;
    const int* src = ei;
    const int* dst = ei + E;

    int nb = (N + 255) / 256;
    int eb = (E + 255) / 256;
    long long st = (long long)E * 16;
    int sb = (int)((st + 255) / 256);

    // degree + dinv (recomputed each launch; deterministic)
    k_deg_init<<<nb, 256>>>(N);
    k_deg_count<<<eb, 256>>>(dst, E);
    k_dinv<<<nb, 256>>>(N);

    // layer 1: hs1 = (x@W1)*dinv, acc=0 ; scatter
    k_gemm<F, 0><<<nb, 256>>>(x, W1, nullptr, nullptr, nullptr, N);
    k_scatter<<<sb, 256>>>(src, dst, E);

    // layer 2: in=relu(dinv*(acc+hs1)+b1); hs2=(in@W2)*dinv, acc=0 ; scatter
    k_gemm<F, 1><<<nb, 256>>>(nullptr, W2, b1, nullptr, nullptr, N);
    k_scatter<<<sb, 256>>>(src, dst, E);

    // head: in=relu(dinv*(acc+hs2)+b2); out = in@Wl + bl
    k_gemm<32, 2><<<nb, 256>>>(nullptr, Wl, b2, bl, out, N);
}